// round 5
// baseline (speedup 1.0000x reference)
#include <cuda_runtime.h>
#include <cstdint>

typedef unsigned long long u64;
typedef unsigned int u32;

#define NB 16
#define C_TOT 84
#define C_CLS 80
#define HW 65536
#define NVEC ((C_CLS * HW) / 4)     // 1310720 float4 per batch
#define NBLK 18                     // blocks per batch (288 total = one wave @2/SM)
#define NT 512
#define LPB (NBLK * NT)             // 9216 lanes per batch
#define ITERS 143                   // ceil(NVEC / LPB); last partial
#define TAILV 2048                  // NVEC - 142*LPB
#define TOPK 100
#define WPB (NBLK * (NT / 32))      // 288 warps per batch
#define CANDS (WPB * 8)             // 2304 candidates per batch

// Fully rewritten each launch -> graph-replay deterministic.
__device__ u64 g_cand[NB][CANDS];
__device__ u32 g_done[NB];          // zero-init; last block resets to 0 each launch

// Key = (ord(v) << 32) | (0xFFFFFFFF - idx): larger value first, then smaller
// index (stable, matches jax.lax.top_k). v >= 0 here, so ord = bits ^ signbit.
__device__ __forceinline__ u64 mkkey(float f, u32 idx) {
    return ((u64)(__float_as_uint(f) ^ 0x80000000u) << 32)
         | (u64)(0xFFFFFFFFu - idx);
}

// Warp-replicated descending top-8 insert (k uniform across warp).
__device__ __forceinline__ void insert8(u64 r[8], u64 k) {
    u64 t = k;
    #pragma unroll
    for (int j = 0; j < 8; j++) {
        bool gt = t > r[j];
        u64 hi = gt ? t : r[j];
        t      = gt ? r[j] : t;
        r[j]   = hi;
    }
}

// Slow path: merge passing elements of one float4 into the warp top-8.
// All control flow inside is warp-uniform (ballots / broadcast keys).
__device__ __forceinline__ void slow4(float4 a, u32 i0, u64 r[8], float& wth) {
    float f[4] = {a.x, a.y, a.z, a.w};
    #pragma unroll
    for (int e = 0; e < 4; e++) {
        bool p = f[e] >= wth;
        u32 em = __ballot_sync(0xFFFFFFFFu, p);
        if (!em) continue;
        u64 key = 0;
        if (p) key = mkkey(f[e], i0 + (u32)e);
        while (em) {
            int src = __ffs(em) - 1; em &= em - 1;
            u64 k = __shfl_sync(0xFFFFFFFFu, key, src);
            if (k > r[7]) insert8(r, k);
        }
        wth = __uint_as_float((u32)(r[7] >> 32) ^ 0x80000000u);
    }
}

__global__ void __launch_bounds__(NT, 2)
fused_kernel(const float* __restrict__ ph, float* __restrict__ out) {
    const int b    = blockIdx.y;
    const int tid  = threadIdx.x;
    const int lane = tid & 31;
    const float4* base = (const float4*)(ph + (size_t)b * C_TOT * HW);
    const int lg = blockIdx.x * NT + tid;          // lane gid within batch

    u64 r[8];
    #pragma unroll
    for (int j = 0; j < 8; j++) r[j] = 1ull << 63; // fake keys < any real key
    float wth = 0.0f;

    // Depth-2 software pipeline. Prefetch at i<ITERS-2 loads up to v(142),
    // which is in-bounds (spills into offset channels; masked at consumption).
    float4 A  = __ldg(base + lg);
    float4 Bv = __ldg(base + lg + LPB);

    for (int i = 0; i < ITERS; i++) {
        float4 N;
        if (i < ITERS - 2) N = __ldg(base + lg + (i + 2) * LPB);
        float4 cv = A;
        if (i == ITERS - 1 && lg >= TAILV) { cv.x = cv.y = cv.z = cv.w = -1.0f; }
        float m = fmaxf(fmaxf(cv.x, cv.y), fmaxf(cv.z, cv.w));
        if (__ballot_sync(0xFFFFFFFFu, m >= wth))
            slow4(cv, (u32)(lg + i * LPB) * 4u, r, wth);
        A = Bv; Bv = N;
    }

    // Emit warp top-8 (replicated in every lane; lane L writes rank L).
    const int wg = blockIdx.x * (NT / 32) + (tid >> 5);
    if (lane < 8) {
        u64 v = r[0];
        if (lane == 1) v = r[1];
        if (lane == 2) v = r[2];
        if (lane == 3) v = r[3];
        if (lane == 4) v = r[4];
        if (lane == 5) v = r[5];
        if (lane == 6) v = r[6];
        if (lane == 7) v = r[7];
        g_cand[b][wg * 8 + lane] = v;
    }

    // ---- last block of this batch performs the merge ----
    __threadfence();
    __syncthreads();
    __shared__ u32 sIsLast;
    if (tid == 0) {
        u32 v = atomicAdd(&g_done[b], 1u);
        sIsLast = (v == NBLK - 1) ? 1u : 0u;
        if (v == NBLK - 1) g_done[b] = 0;     // reset for next graph replay
    }
    __syncthreads();
    if (!sIsLast) return;
    __threadfence();

    __shared__ u64 keys[CANDS];               // 18432 B
    __shared__ u32 hist[2048];                // 8192 B
    __shared__ u64 buf[1024];                 // 8192 B
    __shared__ u32 chunk[64];
    __shared__ u32 sB, sAbove, sCntB, sCnt;

    for (int i = tid; i < CANDS; i += NT) keys[i] = g_cand[b][i];
    __syncthreads();

    // MSB-first radix-select (11-bit digits) for the 100th-largest key.
    u64 prefix = 0, pmask = 0, T = 0;
    u32 nAbove = 0;
    int shift = 53;
    bool done = false;

    for (int lvl = 0; lvl < 3; lvl++) {
        for (int i = tid; i < 2048; i += NT) hist[i] = 0;
        __syncthreads();

        for (int i = tid; i < CANDS; i += NT) {   // warp-uniform trip counts
            u64 k = keys[i];
            u32 bin = ((k & pmask) == prefix) ? (u32)((k >> shift) & 0x7FFu)
                                              : 0xFFFFFFFFu;
            u32 peers = __match_any_sync(0xFFFFFFFFu, bin);
            if (bin != 0xFFFFFFFFu && lane == (int)(__ffs(peers) - 1))
                atomicAdd(&hist[bin], __popc(peers));
        }
        __syncthreads();

        if (tid < 64) {
            u32 s = 0;
            #pragma unroll
            for (int q = 0; q < 32; q++) s += hist[tid * 32 + q];
            chunk[tid] = s;
        }
        __syncthreads();

        if (tid == 0) {
            u32 a = nAbove;
            int B = 0;
            for (int cc = 63; cc >= 0; cc--) {
                if (a + chunk[cc] >= TOPK) {
                    for (int bb = cc * 32 + 31; ; bb--) {
                        if (a + hist[bb] >= TOPK || bb == cc * 32) { B = bb; break; }
                        a += hist[bb];
                    }
                    break;
                }
                a += chunk[cc];
            }
            sB = (u32)B; sAbove = a; sCntB = hist[B];
        }
        __syncthreads();

        u32 sel = sAbove + sCntB;
        if (sel <= 1024u || lvl == 2) {
            T = prefix | ((u64)sB << shift);
            done = true;
        } else {
            prefix |= ((u64)sB << shift);
            pmask  |= (0x7FFull << shift);
            nAbove  = sAbove;
        }
        __syncthreads();
        if (done) break;
        shift -= 11;
    }

    // Compact keys >= T (warp-aggregated append).
    if (tid == 0) sCnt = 0;
    __syncthreads();
    for (int i = tid; i < CANDS; i += NT) {
        u64 k = keys[i];
        bool sel = (k >= T);
        u32 mask = __ballot_sync(0xFFFFFFFFu, sel);
        if (mask) {
            u32 lead = __ffs(mask) - 1;
            u32 basep = 0;
            if ((u32)lane == lead) basep = atomicAdd(&sCnt, __popc(mask));
            basep = __shfl_sync(0xFFFFFFFFu, basep, lead);
            if (sel) {
                u32 pos = basep + __popc(mask & ((1u << lane) - 1u));
                if (pos < 1024u) buf[pos] = k;
            }
        }
    }
    __syncthreads();

    // Exact rank by counting (keys unique), then decode/gather/write.
    u32 M = sCnt; if (M > 1024u) M = 1024u;
    for (u32 t = tid; t < M; t += NT) {
        u64 key = buf[t];
        u32 rank = 0;
        for (u32 j = 0; j < M; j++) rank += (buf[j] > key);
        if (rank < TOPK) {
            u32 ord = (u32)(key >> 32);
            u32 idx = 0xFFFFFFFFu - (u32)key;
            u32 bits = (ord & 0x80000000u) ? (ord ^ 0x80000000u) : ~ord;
            float conf = __uint_as_float(bits);

            int cls = (int)(idx >> 16);          // idx / (256*256)
            int rem = (int)(idx & (HW - 1));
            float y = (float)(rem >> 8);
            float x = (float)(rem & 255);

            const float* gp = ph + ((size_t)b * C_TOT + C_CLS) * HW + rem;
            float o0 = y + gp[0];
            float o1 = x + gp[HW];
            float o2 = gp[2 * HW];
            float o3 = gp[3 * HW];
            float o4 = (float)cls;
            float o5 = conf;
            if (conf < 0.1f) { o0 = o1 = o2 = o3 = o4 = o5 = 0.0f; }

            float* op = out + ((size_t)b * TOPK + rank) * 6;
            op[0] = o0; op[1] = o1; op[2] = o2;
            op[3] = o3; op[4] = o4; op[5] = o5;
        }
    }
}

extern "C" void kernel_launch(void* const* d_in, const int* in_sizes, int n_in,
                              void* d_out, int out_size) {
    (void)in_sizes; (void)n_in; (void)out_size;
    const float* ph = (const float*)d_in[0];
    float* out = (float*)d_out;
    fused_kernel<<<dim3(NBLK, NB), NT>>>(ph, out);
}

// round 6
// speedup vs baseline: 1.3093x; 1.3093x over previous
#include <cuda_runtime.h>
#include <cstdint>

typedef unsigned long long u64;
typedef unsigned int u32;

#define NB 16
#define C_TOT 84
#define C_CLS 80
#define HW 65536
#define NVEC ((C_CLS * HW) / 4)     // 1310720 float4 per batch
#define NBLK 16                     // blocks per batch (256 total, one wave @2/SM)
#define NT 512
#define LPB (NBLK * NT)             // 8192 lanes per batch
#define GROUPS 40                   // 40 groups * 4 vec * 8192 = NVEC exactly
#define TOPK 100
#define WPB (NBLK * (NT / 32))      // 256 warps per batch
#define CANDS (WPB * 8)             // 2048 candidates per batch

// Fully rewritten each launch -> graph-replay deterministic.
__device__ u64 g_cand[NB][CANDS];
__device__ u32 g_done[NB];          // zero-init; last block resets each launch

// Key = (ord(v) << 32) | (0xFFFFFFFF - idx): larger value first, then smaller
// index (stable, matches jax.lax.top_k). v >= 0 here, so ord = bits ^ signbit.
__device__ __forceinline__ u64 mkkey(float f, u32 idx) {
    return ((u64)(__float_as_uint(f) ^ 0x80000000u) << 32)
         | (u64)(0xFFFFFFFFu - idx);
}

// Warp-replicated descending top-8 insert (k uniform across warp).
__device__ __forceinline__ void insert8(u64 r[8], u64 k) {
    u64 t = k;
    #pragma unroll
    for (int j = 0; j < 8; j++) {
        bool gt = t > r[j];
        u64 hi = gt ? t : r[j];
        t      = gt ? r[j] : t;
        r[j]   = hi;
    }
}

__device__ __forceinline__ float max4(float4 a) {
    return fmaxf(fmaxf(a.x, a.y), fmaxf(a.z, a.w));
}

// Slow path for one float4 (warp-uniform control flow).
__device__ __forceinline__ void slowv(float4 a, u32 i0, u64 r[8], float& wth) {
    if (!__ballot_sync(0xFFFFFFFFu, max4(a) >= wth)) return;
    float f[4] = {a.x, a.y, a.z, a.w};
    #pragma unroll
    for (int e = 0; e < 4; e++) {
        bool p = f[e] >= wth;
        u32 em = __ballot_sync(0xFFFFFFFFu, p);
        if (!em) continue;
        u64 key = 0;
        if (p) key = mkkey(f[e], i0 + (u32)e);
        while (em) {
            int src = __ffs(em) - 1; em &= em - 1;
            u64 k = __shfl_sync(0xFFFFFFFFu, key, src);
            if (k > r[7]) insert8(r, k);
        }
        wth = __uint_as_float((u32)(r[7] >> 32) ^ 0x80000000u);
    }
}

__global__ void __launch_bounds__(NT, 2)
fused_kernel(const float* __restrict__ ph, float* __restrict__ out) {
    const int b    = blockIdx.y;
    const int tid  = threadIdx.x;
    const int lane = tid & 31;
    const int lg   = blockIdx.x * NT + tid;        // lane gid within batch
    const float4* __restrict__ p =
        (const float4*)(ph + (size_t)b * C_TOT * HW) + lg;

    u64 r[8];
    #pragma unroll
    for (int j = 0; j < 8; j++) r[j] = 1ull << 63; // fake keys < any real key
    float wth = 0.0f;
    u32 vbase = (u32)lg;                           // vector index of a0 this group

    #pragma unroll 1
    for (int g = 0; g < GROUPS; g++) {
        // 4 independent loads, immediate offsets (MLP=4).
        float4 a0 = __ldg(p);
        float4 a1 = __ldg(p + LPB);
        float4 a2 = __ldg(p + 2 * LPB);
        float4 a3 = __ldg(p + 3 * LPB);
        float m = fmaxf(fmaxf(max4(a0), max4(a1)), fmaxf(max4(a2), max4(a3)));
        if (__ballot_sync(0xFFFFFFFFu, m >= wth)) {
            slowv(a0, vbase * 4u,                 r, wth);
            slowv(a1, (vbase + LPB) * 4u,         r, wth);
            slowv(a2, (vbase + 2u * LPB) * 4u,    r, wth);
            slowv(a3, (vbase + 3u * LPB) * 4u,    r, wth);
        }
        p += 4 * LPB;
        vbase += 4u * LPB;
    }

    // Emit warp top-8 (replicated in every lane; lane L writes rank L).
    const int wg = blockIdx.x * (NT / 32) + (tid >> 5);
    if (lane < 8) {
        u64 v = r[0];
        if (lane == 1) v = r[1];
        if (lane == 2) v = r[2];
        if (lane == 3) v = r[3];
        if (lane == 4) v = r[4];
        if (lane == 5) v = r[5];
        if (lane == 6) v = r[6];
        if (lane == 7) v = r[7];
        g_cand[b][wg * 8 + lane] = v;
    }

    // ---- last block of this batch performs the merge ----
    __threadfence();
    __syncthreads();
    __shared__ u32 sIsLast;
    if (tid == 0) {
        u32 v = atomicAdd(&g_done[b], 1u);
        sIsLast = (v == NBLK - 1) ? 1u : 0u;
        if (v == NBLK - 1) g_done[b] = 0;          // reset for next graph replay
    }
    __syncthreads();
    if (!sIsLast) return;
    __threadfence();

    __shared__ u64 keys[CANDS];                    // 16384 B
    __shared__ u32 hist[2048];                     // 8192 B
    __shared__ u64 buf[1024];                      // 8192 B
    __shared__ u32 chunk[64];
    __shared__ u32 sB, sAbove, sCntB, sCnt;

    for (int i = tid; i < CANDS; i += NT) keys[i] = g_cand[b][i];
    __syncthreads();

    // MSB-first radix-select (11-bit digits) for the 100th-largest key.
    u64 prefix = 0, pmask = 0, T = 0;
    u32 nAbove = 0;
    int shift = 53;
    bool done = false;

    for (int lvl = 0; lvl < 3; lvl++) {
        for (int i = tid; i < 2048; i += NT) hist[i] = 0;
        __syncthreads();

        for (int i = tid; i < CANDS; i += NT) {    // warp-uniform trip counts
            u64 k = keys[i];
            u32 bin = ((k & pmask) == prefix) ? (u32)((k >> shift) & 0x7FFu)
                                              : 0xFFFFFFFFu;
            u32 peers = __match_any_sync(0xFFFFFFFFu, bin);
            if (bin != 0xFFFFFFFFu && lane == (int)(__ffs(peers) - 1))
                atomicAdd(&hist[bin], __popc(peers));
        }
        __syncthreads();

        if (tid < 64) {
            u32 s = 0;
            #pragma unroll
            for (int q = 0; q < 32; q++) s += hist[tid * 32 + q];
            chunk[tid] = s;
        }
        __syncthreads();

        if (tid == 0) {
            u32 a = nAbove;
            int B = 0;
            for (int cc = 63; cc >= 0; cc--) {
                if (a + chunk[cc] >= TOPK) {
                    for (int bb = cc * 32 + 31; ; bb--) {
                        if (a + hist[bb] >= TOPK || bb == cc * 32) { B = bb; break; }
                        a += hist[bb];
                    }
                    break;
                }
                a += chunk[cc];
            }
            sB = (u32)B; sAbove = a; sCntB = hist[B];
        }
        __syncthreads();

        u32 sel = sAbove + sCntB;
        if (sel <= 1024u || lvl == 2) {
            T = prefix | ((u64)sB << shift);
            done = true;
        } else {
            prefix |= ((u64)sB << shift);
            pmask  |= (0x7FFull << shift);
            nAbove  = sAbove;
        }
        __syncthreads();
        if (done) break;
        shift -= 11;
    }

    // Compact keys >= T (warp-aggregated append).
    if (tid == 0) sCnt = 0;
    __syncthreads();
    for (int i = tid; i < CANDS; i += NT) {
        u64 k = keys[i];
        bool sel = (k >= T);
        u32 mask = __ballot_sync(0xFFFFFFFFu, sel);
        if (mask) {
            u32 lead = __ffs(mask) - 1;
            u32 basep = 0;
            if ((u32)lane == lead) basep = atomicAdd(&sCnt, __popc(mask));
            basep = __shfl_sync(0xFFFFFFFFu, basep, lead);
            if (sel) {
                u32 pos = basep + __popc(mask & ((1u << lane) - 1u));
                if (pos < 1024u) buf[pos] = k;
            }
        }
    }
    __syncthreads();

    // Exact rank by counting (keys unique), then decode/gather/write.
    u32 M = sCnt; if (M > 1024u) M = 1024u;
    for (u32 t = tid; t < M; t += NT) {
        u64 key = buf[t];
        u32 rank = 0;
        for (u32 j = 0; j < M; j++) rank += (buf[j] > key);
        if (rank < TOPK) {
            u32 ord = (u32)(key >> 32);
            u32 idx = 0xFFFFFFFFu - (u32)key;
            u32 bits = (ord & 0x80000000u) ? (ord ^ 0x80000000u) : ~ord;
            float conf = __uint_as_float(bits);

            int cls = (int)(idx >> 16);            // idx / (256*256)
            int rem = (int)(idx & (HW - 1));
            float y = (float)(rem >> 8);
            float x = (float)(rem & 255);

            const float* gp = ph + ((size_t)b * C_TOT + C_CLS) * HW + rem;
            float o0 = y + gp[0];
            float o1 = x + gp[HW];
            float o2 = gp[2 * HW];
            float o3 = gp[3 * HW];
            float o4 = (float)cls;
            float o5 = conf;
            if (conf < 0.1f) { o0 = o1 = o2 = o3 = o4 = o5 = 0.0f; }

            float* op = out + ((size_t)b * TOPK + rank) * 6;
            op[0] = o0; op[1] = o1; op[2] = o2;
            op[3] = o3; op[4] = o4; op[5] = o5;
        }
    }
}

extern "C" void kernel_launch(void* const* d_in, const int* in_sizes, int n_in,
                              void* d_out, int out_size) {
    (void)in_sizes; (void)n_in; (void)out_size;
    const float* ph = (const float*)d_in[0];
    float* out = (float*)d_out;
    fused_kernel<<<dim3(NBLK, NB), NT>>>(ph, out);
}

// round 8
// speedup vs baseline: 1.5561x; 1.1885x over previous
#include <cuda_runtime.h>
#include <cstdint>

typedef unsigned long long u64;
typedef unsigned int u32;

#define NB 16
#define C_TOT 84
#define C_CLS 80
#define HW 65536
#define NVEC ((C_CLS * HW) / 4)     // 1310720 float4 per batch
#define NBLK 16                     // blocks per batch (256 total, one wave @2/SM)
#define NT 512
#define LPB (NBLK * NT)             // 8192 lanes per batch
#define GROUPS 40                   // 40 groups * 4 vec * 8192 = NVEC exactly
#define TOPK 100
#define WPB (NBLK * (NT / 32))      // 256 warps per batch
#define CANDS (WPB * 8)             // 2048 candidates per batch

// Fully rewritten each launch -> graph-replay deterministic.
__device__ u64 g_cand[NB][CANDS];
__device__ u32 g_done[NB];          // zero-init; last block resets each launch

// Key = (ord(v) << 32) | (0xFFFFFFFF - idx): larger value first, then smaller
// index (stable, matches jax.lax.top_k). v >= 0 here, so ord = bits ^ signbit.
__device__ __forceinline__ u64 mkkey(float f, u32 idx) {
    return ((u64)(__float_as_uint(f) ^ 0x80000000u) << 32)
         | (u64)(0xFFFFFFFFu - idx);
}

// Warp-replicated descending top-8 insert (k uniform across warp).
__device__ __forceinline__ void insert8(u64 r[8], u64 k) {
    u64 t = k;
    #pragma unroll
    for (int j = 0; j < 8; j++) {
        bool gt = t > r[j];
        u64 hi = gt ? t : r[j];
        t      = gt ? r[j] : t;
        r[j]   = hi;
    }
}

__device__ __forceinline__ float max4(float4 a) {
    return fmaxf(fmaxf(a.x, a.y), fmaxf(a.z, a.w));
}

// Slow path for one float4 (warp-uniform control flow).
__device__ __forceinline__ void slowv(float4 a, u32 i0, u64 r[8], float& wth) {
    if (!__ballot_sync(0xFFFFFFFFu, max4(a) >= wth)) return;
    float f[4] = {a.x, a.y, a.z, a.w};
    #pragma unroll
    for (int e = 0; e < 4; e++) {
        bool p = f[e] >= wth;
        u32 em = __ballot_sync(0xFFFFFFFFu, p);
        if (!em) continue;
        u64 key = 0;
        if (p) key = mkkey(f[e], i0 + (u32)e);
        while (em) {
            int src = __ffs(em) - 1; em &= em - 1;
            u64 k = __shfl_sync(0xFFFFFFFFu, key, src);
            if (k > r[7]) insert8(r, k);
        }
        // r[7] value (fake key decodes to 0.0f) can only raise the threshold.
        wth = fmaxf(wth, __uint_as_float((u32)(r[7] >> 32) ^ 0x80000000u));
    }
}

__global__ void __launch_bounds__(NT, 2)
fused_kernel(const float* __restrict__ ph, float* __restrict__ out) {
    const int b    = blockIdx.y;
    const int tid  = threadIdx.x;
    const int lane = tid & 31;
    const int lg   = blockIdx.x * NT + tid;        // lane gid within batch
    const float4* __restrict__ p =
        (const float4*)(ph + (size_t)b * C_TOT * HW) + lg;

    u64 r[8];
    #pragma unroll
    for (int j = 0; j < 8; j++) r[j] = 1ull << 63; // fake keys < any real key
    u32 vbase = (u32)lg;                           // vector index of a0

    // ---- group 0: warm-up threshold, then normal processing ----
    float wth;
    {
        float4 a0 = __ldg(p);
        float4 a1 = __ldg(p + LPB);
        float4 a2 = __ldg(p + 2 * LPB);
        float4 a3 = __ldg(p + 3 * LPB);
        // 8th-largest of the 32 lane-maxes: conservative lower bound on the
        // warp's true 8th-best element (8 distinct elements), so no top-8
        // member is ever filtered out.
        float v = fmaxf(fmaxf(max4(a0), max4(a1)), fmaxf(max4(a2), max4(a3)));
        float m = 0.0f;
        #pragma unroll
        for (int j = 0; j < 8; j++) {
            m = v;
            #pragma unroll
            for (int o = 16; o; o >>= 1)
                m = fmaxf(m, __shfl_xor_sync(0xFFFFFFFFu, m, o));
            if (v == m) v = -1.0f;   // remove winner(s); ties only lower wth
        }
        wth = m;
        slowv(a0, vbase * 4u,              r, wth);
        slowv(a1, (vbase + LPB) * 4u,      r, wth);
        slowv(a2, (vbase + 2u * LPB) * 4u, r, wth);
        slowv(a3, (vbase + 3u * LPB) * 4u, r, wth);
        p += 4 * LPB;
        vbase += 4u * LPB;
    }

    #pragma unroll 1
    for (int g = 1; g < GROUPS; g++) {
        // 4 independent loads, immediate offsets (MLP=4).
        float4 a0 = __ldg(p);
        float4 a1 = __ldg(p + LPB);
        float4 a2 = __ldg(p + 2 * LPB);
        float4 a3 = __ldg(p + 3 * LPB);
        float m = fmaxf(fmaxf(max4(a0), max4(a1)), fmaxf(max4(a2), max4(a3)));
        if (__ballot_sync(0xFFFFFFFFu, m >= wth)) {
            slowv(a0, vbase * 4u,              r, wth);
            slowv(a1, (vbase + LPB) * 4u,      r, wth);
            slowv(a2, (vbase + 2u * LPB) * 4u, r, wth);
            slowv(a3, (vbase + 3u * LPB) * 4u, r, wth);
        }
        p += 4 * LPB;
        vbase += 4u * LPB;
    }

    // Emit warp top-8 (replicated in every lane; lane L writes rank L).
    const int wg = blockIdx.x * (NT / 32) + (tid >> 5);
    if (lane < 8) {
        u64 v = r[0];
        if (lane == 1) v = r[1];
        if (lane == 2) v = r[2];
        if (lane == 3) v = r[3];
        if (lane == 4) v = r[4];
        if (lane == 5) v = r[5];
        if (lane == 6) v = r[6];
        if (lane == 7) v = r[7];
        g_cand[b][wg * 8 + lane] = v;
    }

    // ---- last block of this batch performs the merge ----
    __threadfence();
    __syncthreads();
    __shared__ u32 sIsLast;
    if (tid == 0) {
        u32 v = atomicAdd(&g_done[b], 1u);
        sIsLast = (v == NBLK - 1) ? 1u : 0u;
        if (v == NBLK - 1) g_done[b] = 0;          // reset for next graph replay
    }
    __syncthreads();
    if (!sIsLast) return;
    __threadfence();

    __shared__ u64 keys[CANDS];                    // 16384 B
    __shared__ u32 hist[2048];                     // 8192 B
    __shared__ u64 buf[1024];                      // 8192 B
    __shared__ u32 chunk[64];
    __shared__ u32 sB, sAbove, sCntB, sCnt;

    for (int i = tid; i < CANDS; i += NT) keys[i] = g_cand[b][i];
    __syncthreads();

    // MSB-first radix-select (11-bit digits) for the 100th-largest key.
    u64 prefix = 0, pmask = 0, T = 0;
    u32 nAbove = 0;
    int shift = 53;
    bool done = false;

    for (int lvl = 0; lvl < 3; lvl++) {
        for (int i = tid; i < 2048; i += NT) hist[i] = 0;
        __syncthreads();

        for (int i = tid; i < CANDS; i += NT) {    // warp-uniform trip counts
            u64 k = keys[i];
            u32 bin = ((k & pmask) == prefix) ? (u32)((k >> shift) & 0x7FFu)
                                              : 0xFFFFFFFFu;
            u32 peers = __match_any_sync(0xFFFFFFFFu, bin);
            if (bin != 0xFFFFFFFFu && lane == (int)(__ffs(peers) - 1))
                atomicAdd(&hist[bin], __popc(peers));
        }
        __syncthreads();

        if (tid < 64) {
            u32 s = 0;
            #pragma unroll
            for (int q = 0; q < 32; q++) s += hist[tid * 32 + q];
            chunk[tid] = s;
        }
        __syncthreads();

        if (tid == 0) {
            u32 a = nAbove;
            int B = 0;
            for (int cc = 63; cc >= 0; cc--) {
                if (a + chunk[cc] >= TOPK) {
                    for (int bb = cc * 32 + 31; ; bb--) {
                        if (a + hist[bb] >= TOPK || bb == cc * 32) { B = bb; break; }
                        a += hist[bb];
                    }
                    break;
                }
                a += chunk[cc];
            }
            sB = (u32)B; sAbove = a; sCntB = hist[B];
        }
        __syncthreads();

        u32 sel = sAbove + sCntB;
        if (sel <= 1024u || lvl == 2) {
            T = prefix | ((u64)sB << shift);
            done = true;
        } else {
            prefix |= ((u64)sB << shift);
            pmask  |= (0x7FFull << shift);
            nAbove  = sAbove;
        }
        __syncthreads();
        if (done) break;
        shift -= 11;
    }

    // Compact keys >= T (warp-aggregated append).
    if (tid == 0) sCnt = 0;
    __syncthreads();
    for (int i = tid; i < CANDS; i += NT) {
        u64 k = keys[i];
        bool sel = (k >= T);
        u32 mask = __ballot_sync(0xFFFFFFFFu, sel);
        if (mask) {
            u32 lead = __ffs(mask) - 1;
            u32 basep = 0;
            if ((u32)lane == lead) basep = atomicAdd(&sCnt, __popc(mask));
            basep = __shfl_sync(0xFFFFFFFFu, basep, lead);
            if (sel) {
                u32 pos = basep + __popc(mask & ((1u << lane) - 1u));
                if (pos < 1024u) buf[pos] = k;
            }
        }
    }
    __syncthreads();

    // Exact rank by counting (keys unique), then decode/gather/write.
    u32 M = sCnt; if (M > 1024u) M = 1024u;
    for (u32 t = tid; t < M; t += NT) {
        u64 key = buf[t];
        u32 rank = 0;
        for (u32 j = 0; j < M; j++) rank += (buf[j] > key);
        if (rank < TOPK) {
            u32 ord = (u32)(key >> 32);
            u32 idx = 0xFFFFFFFFu - (u32)key;
            u32 bits = (ord & 0x80000000u) ? (ord ^ 0x80000000u) : ~ord;
            float conf = __uint_as_float(bits);

            int cls = (int)(idx >> 16);            // idx / (256*256)
            int rem = (int)(idx & (HW - 1));
            float y = (float)(rem >> 8);
            float x = (float)(rem & 255);

            const float* gp = ph + ((size_t)b * C_TOT + C_CLS) * HW + rem;
            float o0 = y + gp[0];
            float o1 = x + gp[HW];
            float o2 = gp[2 * HW];
            float o3 = gp[3 * HW];
            float o4 = (float)cls;
            float o5 = conf;
            if (conf < 0.1f) { o0 = o1 = o2 = o3 = o4 = o5 = 0.0f; }

            float* op = out + ((size_t)b * TOPK + rank) * 6;
            op[0] = o0; op[1] = o1; op[2] = o2;
            op[3] = o3; op[4] = o4; op[5] = o5;
        }
    }
}

extern "C" void kernel_launch(void* const* d_in, const int* in_sizes, int n_in,
                              void* d_out, int out_size) {
    (void)in_sizes; (void)n_in; (void)out_size;
    const float* ph = (const float*)d_in[0];
    float* out = (float*)d_out;
    fused_kernel<<<dim3(NBLK, NB), NT>>>(ph, out);
}